// round 5
// baseline (speedup 1.0000x reference)
#include <cuda_runtime.h>
#include <cstdint>
#include <cstddef>

#define B_   8
#define C_   192
#define HW_  16384
#define D_   64

typedef unsigned long long u64;

// ---------------- static device scratch (allocation-free rule) ----------------
__device__ float g_G[(size_t)B_ * HW_ * 192];      // gate pre-activations [pix][192]
__device__ float g_Hs[2][(size_t)B_ * HW_ * D_];   // per-axis hidden sum (fwd+bwd): [0]=horiz, [1]=vert
__device__ float g_Wc[C_ * 192];                   // folded input weights, stored [c][g]
__device__ float g_bc[192];
__device__ float g_Wot[D_ * C_];                   // Wo^T stored [d][c]

// ---------------- f32x2 helpers ----------------
__device__ __forceinline__ void fma2(u64 &acc, u64 a, u64 b) {
    asm("fma.rn.f32x2 %0, %1, %2, %0;" : "+l"(acc) : "l"(a), "l"(b));
}
__device__ __forceinline__ u64 pack2(float x, float y) {
    u64 r; asm("mov.b64 %0, {%1, %2};" : "=l"(r) : "f"(x), "f"(y)); return r;
}
__device__ __forceinline__ float2 unpack2(u64 v) {
    float2 r; asm("mov.b64 {%0, %1}, %2;" : "=f"(r.x), "=f"(r.y) : "l"(v)); return r;
}
__device__ __forceinline__ float sigm(float x) { return 1.f / (1.f + __expf(-x)); }

// ---------------- kernel 1: fold weights ----------------
__global__ void prep_kernel(const float* __restrict__ Wi, const float* __restrict__ bi,
                            const float* __restrict__ Wih, const float* __restrict__ bih,
                            const float* __restrict__ Wo) {
    const int bid = blockIdx.x;
    const int c = threadIdx.x;
    if (bid < 192) {
        const int g = bid;
        float acc = 0.f;
        #pragma unroll 8
        for (int d = 0; d < 64; d++) acc += Wih[g * 64 + d] * Wi[d * 192 + c];
        g_Wc[c * 192 + g] = acc;
        if (c == 0) {
            float s = bih[g];
            for (int d = 0; d < 64; d++) s += Wih[g * 64 + d] * bi[d];
            g_bc[g] = s;
        }
    } else {
        const int d = bid - 192;
        g_Wot[d * 192 + c] = Wo[c * 64 + d];
    }
}

// ---------------- kernel 2: G = Wc @ x + bc  (f32x2, pixel pairs) ----------------
// block: 256 pixels x 64 gates, K=192 in chunks of 16. 256 threads.
// thread: 8 pixels (pairs (2tx,2tx+1) and (2tx+64,2tx+65)) x 8 gates (8ty..8ty+7).
__global__ void __launch_bounds__(256) g_gemm_kernel(const float* __restrict__ x) {
    const int pblk = blockIdx.x;          // 0..511
    const int b  = pblk >> 6;             // 64 pixel blocks per image
    const int p0 = (pblk & 63) * 256;
    const int g0 = blockIdx.y * 64;
    const int tid = threadIdx.x;
    const int tx = tid & 31;              // pixel cluster (4 px low half, 4 px high half)
    const int ty = tid >> 5;              // gate group (== warp id)

    __shared__ __align__(16) float  sX[16][256];
    __shared__ __align__(16) float2 sWd[16][64];   // duplicated weights (w,w)

    u64 acc[2][2][8];                     // [half][pair-in-half][gate]
    #pragma unroll
    for (int h = 0; h < 2; h++)
        #pragma unroll
        for (int p = 0; p < 2; p++)
            #pragma unroll
            for (int j = 0; j < 8; j++) acc[h][p][j] = 0ULL;

    const float* xb = x + (size_t)b * C_ * HW_ + p0;

    for (int c0i = 0; c0i < 192; c0i += 16) {
        #pragma unroll
        for (int i = 0; i < 4; i++) {
            int lin = tid + i * 256;               // 1024 float4 slots
            int cc = lin >> 6, q4 = lin & 63;
            ((float4*)sX[cc])[q4] = *(const float4*)(xb + (size_t)(c0i + cc) * HW_ + q4 * 4);
        }
        #pragma unroll
        for (int i = 0; i < 4; i++) {
            int lin = tid + i * 256;               // 1024 weight elems
            int cc = lin >> 6, gg = lin & 63;
            float w = g_Wc[(c0i + cc) * 192 + g0 + gg];
            sWd[cc][gg] = make_float2(w, w);
        }
        __syncthreads();
        #pragma unroll
        for (int cc = 0; cc < 16; cc++) {
            longlong2 xA = *(const longlong2*)&sX[cc][4 * tx];        // pixels 4tx..4tx+3
            longlong2 xB = *(const longlong2*)&sX[cc][128 + 4 * tx];  // pixels 128+4tx..
            const longlong2* wp = (const longlong2*)&sWd[cc][8 * ty]; // broadcast
            longlong2 w01 = wp[0], w23 = wp[1], w45 = wp[2], w67 = wp[3];
            u64 wd[8] = { (u64)w01.x, (u64)w01.y, (u64)w23.x, (u64)w23.y,
                          (u64)w45.x, (u64)w45.y, (u64)w67.x, (u64)w67.y };
            #pragma unroll
            for (int j = 0; j < 8; j++) {
                fma2(acc[0][0][j], wd[j], (u64)xA.x);
                fma2(acc[0][1][j], wd[j], (u64)xA.y);
                fma2(acc[1][0][j], wd[j], (u64)xB.x);
                fma2(acc[1][1][j], wd[j], (u64)xB.y);
            }
        }
        __syncthreads();
    }

    float bc[8];
    *(float4*)&bc[0] = *(const float4*)&g_bc[g0 + 8 * ty];
    *(float4*)&bc[4] = *(const float4*)&g_bc[g0 + 8 * ty + 4];

    #pragma unroll
    for (int h = 0; h < 2; h++) {
        #pragma unroll
        for (int p = 0; p < 2; p++) {
            const size_t q = (size_t)b * HW_ + p0 + h * 128 + 4 * tx + 2 * p;
            float2 v[8];
            #pragma unroll
            for (int j = 0; j < 8; j++) v[j] = unpack2(acc[h][p][j]);
            float* gp0 = &g_G[q * 192 + g0 + 8 * ty];
            ((float4*)gp0)[0] = make_float4(v[0].x + bc[0], v[1].x + bc[1], v[2].x + bc[2], v[3].x + bc[3]);
            ((float4*)gp0)[1] = make_float4(v[4].x + bc[4], v[5].x + bc[5], v[6].x + bc[6], v[7].x + bc[7]);
            float* gp1 = gp0 + 192;
            ((float4*)gp1)[0] = make_float4(v[0].y + bc[0], v[1].y + bc[1], v[2].y + bc[2], v[3].y + bc[3]);
            ((float4*)gp1)[1] = make_float4(v[4].y + bc[4], v[5].y + bc[5], v[6].y + bc[6], v[7].y + bc[7]);
        }
    }
}

// ---------------- kernel 3: GRU scans (f32x2 over d-pairs, fwd+bwd per block) ----------------
// 2048 blocks: [0,1024) horizontal, [1024,2048) vertical. 192 threads.
// Thread g holds W_hh row g as 32 packed u64 (natural d-pairs).
// fwd+bwd hidden states summed into ONE buffer per axis (RMW when t>=64;
// ordering between the two writers of a pixel is guaranteed by per-step __syncthreads).
__global__ void __launch_bounds__(192) scan_kernel(const float* __restrict__ Whh,
                                                   const float* __restrict__ bhh) {
    const int l    = blockIdx.x;
    const int axis = l >> 10;
    const int ll   = l & 1023;
    const int b    = ll >> 7;
    const int lane = ll & 127;
    const int g    = threadIdx.x;

    __shared__ __align__(16) float h[2][64];
    __shared__ float hg[2][192];

    u64 w2[32];
    {
        const float2* wr = (const float2*)(Whh + g * 64);
        #pragma unroll
        for (int k = 0; k < 32; k++) {
            float2 w = wr[k];
            w2[k] = pack2(w.x, w.y);
        }
    }
    const float bh = bhh[g];

    if (g < 64) { h[0][g] = 0.f; h[1][g] = 0.f; }
    __syncthreads();

    const float* Gb = g_G + (size_t)b * HW_ * 192;
    float* outS = g_Hs[axis] + (size_t)b * HW_ * 64;
    const int pstride = axis ? 128 : 1;
    const int pbase   = axis ? lane : lane * 128;

    for (int t = 0; t < 128; t++) {
        const u64* hF = (const u64*)h[0];
        const u64* hB = (const u64*)h[1];
        u64 a0 = 0ULL, a1 = 0ULL, c0 = 0ULL, c1 = 0ULL;
        #pragma unroll
        for (int k = 0; k < 32; k += 2) {
            fma2(a0, w2[k],     hF[k]);
            fma2(a1, w2[k + 1], hF[k + 1]);
            fma2(c0, w2[k],     hB[k]);
            fma2(c1, w2[k + 1], hB[k + 1]);
        }
        float2 fa = unpack2(a0), fb = unpack2(a1);
        float2 fc = unpack2(c0), fd = unpack2(c1);
        hg[0][g] = bh + (fa.x + fa.y) + (fb.x + fb.y);
        hg[1][g] = bh + (fc.x + fc.y) + (fd.x + fd.y);
        __syncthreads();
        if (g < 128) {
            const int dir = g >> 6;                 // 0 fwd, 1 bwd
            const int d   = g & 63;
            const int tt  = dir ? (127 - t) : t;
            const int p   = pbase + tt * pstride;
            const float* Gp = Gb + (size_t)p * 192;
            const float xr = Gp[d], xz = Gp[64 + d], xn = Gp[128 + d];
            const float hr = hg[dir][d], hz = hg[dir][64 + d], hn = hg[dir][128 + d];
            const float r = sigm(xr + hr);
            const float z = sigm(xz + hz);
            const float pre = xn + r * hn;
            const float n = 2.f / (1.f + __expf(-2.f * pre)) - 1.f;   // tanh
            const float hnew = (1.f - z) * n + z * h[dir][d];
            h[dir][d] = hnew;
            float* o = outS + (size_t)p * 64 + d;
            if (t < 64) *o = hnew;                  // first writer of this pixel
            else        *o = *o + hnew;             // second writer: accumulate
        }
        __syncthreads();
    }
}

// ---------------- kernel 4: out = Wo @ avg4(h) + bo  (f32x2, coalesced stores) ----------------
// block: 64 pixels x 64 channels, K=64. 256 threads; thread: 4 px (pixel pair) x 4 ch.
__global__ void __launch_bounds__(256) out_gemm_kernel(const float* __restrict__ bo,
                                                       float* __restrict__ out) {
    const int bx = blockIdx.x;            // 0..2047
    const int b  = bx >> 8;
    const int p0 = (bx & 255) * 64;
    const int c0 = blockIdx.y * 64;
    const int tid = threadIdx.x;
    const int tx = tid & 15;              // pixel group of 4 (fast -> coalesced stores)
    const int ty = tid >> 4;              // channel group of 4

    __shared__ __align__(16) float sH[64][66];   // d-major: sH[d][pixel]
    __shared__ __align__(16) float sW[64][64];   // sW[d][channel]

    const size_t base = ((size_t)b * HW_ + p0) * 64;
    const float* hH = g_Hs[0] + base;
    const float* hV = g_Hs[1] + base;

    #pragma unroll
    for (int i = 0; i < 16; i++) {
        int lin = tid + i * 256;
        int pp = lin >> 6, dd = lin & 63;         // dd fast -> coalesced global reads
        sH[dd][pp] = 0.25f * (hH[(size_t)pp * 64 + dd] + hV[(size_t)pp * 64 + dd]);
    }
    #pragma unroll
    for (int i = 0; i < 16; i++) {
        int lin = tid + i * 256;
        int dd = lin >> 6, cc = lin & 63;
        sW[dd][cc] = g_Wot[dd * 192 + c0 + cc];
    }
    __syncthreads();

    u64 acc[4][2];
    #pragma unroll
    for (int j = 0; j < 4; j++) { acc[j][0] = 0ULL; acc[j][1] = 0ULL; }

    #pragma unroll
    for (int dd = 0; dd < 64; dd++) {
        const u64* ap = (const u64*)&sH[dd][4 * tx];     // 8B-aligned (row stride 66 floats)
        u64 aLo = ap[0], aHi = ap[1];                    // pixels (4tx,4tx+1),(4tx+2,4tx+3)
        float4 wv = *(const float4*)&sW[dd][4 * ty];
        u64 wd[4] = { pack2(wv.x, wv.x), pack2(wv.y, wv.y),
                      pack2(wv.z, wv.z), pack2(wv.w, wv.w) };
        #pragma unroll
        for (int j = 0; j < 4; j++) {
            fma2(acc[j][0], wd[j], aLo);
            fma2(acc[j][1], wd[j], aHi);
        }
    }

    #pragma unroll
    for (int j = 0; j < 4; j++) {
        const int c = c0 + 4 * ty + j;
        const float bv = bo[c];
        float2 lo = unpack2(acc[j][0]), hi = unpack2(acc[j][1]);
        float4 v = make_float4(lo.x + bv, lo.y + bv, hi.x + bv, hi.y + bv);
        *(float4*)&out[((size_t)b * 192 + c) * HW_ + p0 + 4 * tx] = v;   // coalesced
    }
}

// ---------------- launch ----------------
extern "C" void kernel_launch(void* const* d_in, const int* in_sizes, int n_in,
                              void* d_out, int out_size) {
    const float* x   = (const float*)d_in[0];
    const float* Wi  = (const float*)d_in[1];
    const float* bi  = (const float*)d_in[2];
    const float* Wih = (const float*)d_in[3];
    const float* Whh = (const float*)d_in[4];
    const float* bih = (const float*)d_in[5];
    const float* bhh = (const float*)d_in[6];
    const float* Wo  = (const float*)d_in[7];
    const float* bo  = (const float*)d_in[8];
    float* out = (float*)d_out;

    prep_kernel<<<256, 192>>>(Wi, bi, Wih, bih, Wo);
    g_gemm_kernel<<<dim3(512, 3), 256>>>(x);
    scan_kernel<<<2048, 192>>>(Whh, bhh);
    out_gemm_kernel<<<dim3(2048, 3), 256>>>(bo, out);
}

// round 6
// speedup vs baseline: 1.0187x; 1.0187x over previous
#include <cuda_runtime.h>
#include <cstdint>
#include <cstddef>

#define B_   8
#define C_   192
#define HW_  16384
#define D_   64

typedef unsigned long long u64;

// ---------------- static device scratch (allocation-free rule) ----------------
__device__ float g_G[(size_t)B_ * HW_ * 192];      // gate pre-activations [pix][192]
__device__ float g_Hs[2][(size_t)B_ * HW_ * D_];   // per-axis hidden sum (fwd+bwd)
__device__ float g_Wc[C_ * 192];                   // folded input weights [c][g]
__device__ float g_bc[192];
__device__ float g_Wot[D_ * C_];                   // Wo^T [d][c]

// ---------------- f32x2 helpers ----------------
__device__ __forceinline__ void fma2(u64 &acc, u64 a, u64 b) {
    asm("fma.rn.f32x2 %0, %1, %2, %0;" : "+l"(acc) : "l"(a), "l"(b));
}
__device__ __forceinline__ u64 pack2(float x, float y) {
    u64 r; asm("mov.b64 %0, {%1, %2};" : "=l"(r) : "f"(x), "f"(y)); return r;
}
__device__ __forceinline__ float2 unpack2(u64 v) {
    float2 r; asm("mov.b64 {%0, %1}, %2;" : "=f"(r.x), "=f"(r.y) : "l"(v)); return r;
}
__device__ __forceinline__ float sigm(float x) { return 1.f / (1.f + __expf(-x)); }

// ---------------- kernel 1: fold weights ----------------
__global__ void prep_kernel(const float* __restrict__ Wi, const float* __restrict__ bi,
                            const float* __restrict__ Wih, const float* __restrict__ bih,
                            const float* __restrict__ Wo) {
    const int bid = blockIdx.x;
    const int c = threadIdx.x;
    if (bid < 192) {
        const int g = bid;
        float acc = 0.f;
        #pragma unroll 8
        for (int d = 0; d < 64; d++) acc += Wih[g * 64 + d] * Wi[d * 192 + c];
        g_Wc[c * 192 + g] = acc;
        if (c == 0) {
            float s = bih[g];
            for (int d = 0; d < 64; d++) s += Wih[g * 64 + d] * bi[d];
            g_bc[g] = s;
        }
    } else {
        const int d = bid - 192;
        g_Wot[d * 192 + c] = Wo[c * 64 + d];
    }
}

// ---------------- kernel 2: G = Wc @ x + bc  (f32x2, pixel pairs) ----------------
__global__ void __launch_bounds__(256) g_gemm_kernel(const float* __restrict__ x) {
    const int pblk = blockIdx.x;          // 0..511
    const int b  = pblk >> 6;
    const int p0 = (pblk & 63) * 256;
    const int g0 = blockIdx.y * 64;
    const int tid = threadIdx.x;
    const int tx = tid & 31;
    const int ty = tid >> 5;

    __shared__ __align__(16) float  sX[16][256];
    __shared__ __align__(16) float2 sWd[16][64];

    u64 acc[2][2][8];
    #pragma unroll
    for (int h = 0; h < 2; h++)
        #pragma unroll
        for (int p = 0; p < 2; p++)
            #pragma unroll
            for (int j = 0; j < 8; j++) acc[h][p][j] = 0ULL;

    const float* xb = x + (size_t)b * C_ * HW_ + p0;

    for (int c0i = 0; c0i < 192; c0i += 16) {
        #pragma unroll
        for (int i = 0; i < 4; i++) {
            int lin = tid + i * 256;
            int cc = lin >> 6, q4 = lin & 63;
            ((float4*)sX[cc])[q4] = *(const float4*)(xb + (size_t)(c0i + cc) * HW_ + q4 * 4);
        }
        #pragma unroll
        for (int i = 0; i < 4; i++) {
            int lin = tid + i * 256;
            int cc = lin >> 6, gg = lin & 63;
            float w = g_Wc[(c0i + cc) * 192 + g0 + gg];
            sWd[cc][gg] = make_float2(w, w);
        }
        __syncthreads();
        #pragma unroll
        for (int cc = 0; cc < 16; cc++) {
            longlong2 xA = *(const longlong2*)&sX[cc][4 * tx];
            longlong2 xB = *(const longlong2*)&sX[cc][128 + 4 * tx];
            const longlong2* wp = (const longlong2*)&sWd[cc][8 * ty];
            longlong2 w01 = wp[0], w23 = wp[1], w45 = wp[2], w67 = wp[3];
            u64 wd[8] = { (u64)w01.x, (u64)w01.y, (u64)w23.x, (u64)w23.y,
                          (u64)w45.x, (u64)w45.y, (u64)w67.x, (u64)w67.y };
            #pragma unroll
            for (int j = 0; j < 8; j++) {
                fma2(acc[0][0][j], wd[j], (u64)xA.x);
                fma2(acc[0][1][j], wd[j], (u64)xA.y);
                fma2(acc[1][0][j], wd[j], (u64)xB.x);
                fma2(acc[1][1][j], wd[j], (u64)xB.y);
            }
        }
        __syncthreads();
    }

    float bc[8];
    *(float4*)&bc[0] = *(const float4*)&g_bc[g0 + 8 * ty];
    *(float4*)&bc[4] = *(const float4*)&g_bc[g0 + 8 * ty + 4];

    #pragma unroll
    for (int h = 0; h < 2; h++) {
        #pragma unroll
        for (int p = 0; p < 2; p++) {
            const size_t q = (size_t)b * HW_ + p0 + h * 128 + 4 * tx + 2 * p;
            float2 v[8];
            #pragma unroll
            for (int j = 0; j < 8; j++) v[j] = unpack2(acc[h][p][j]);
            float* gp0 = &g_G[q * 192 + g0 + 8 * ty];
            ((float4*)gp0)[0] = make_float4(v[0].x + bc[0], v[1].x + bc[1], v[2].x + bc[2], v[3].x + bc[3]);
            ((float4*)gp0)[1] = make_float4(v[4].x + bc[4], v[5].x + bc[5], v[6].x + bc[6], v[7].x + bc[7]);
            float* gp1 = gp0 + 192;
            ((float4*)gp1)[0] = make_float4(v[0].y + bc[0], v[1].y + bc[1], v[2].y + bc[2], v[3].y + bc[3]);
            ((float4*)gp1)[1] = make_float4(v[4].y + bc[4], v[5].y + bc[5], v[6].y + bc[6], v[7].y + bc[7]);
        }
    }
}

// ---------------- kernel 3: GRU scans, 4 lines x (fwd+bwd) = 8 seqs per block ----------------
// 512 blocks: [0,256) horizontal, [256,512) vertical. 192 threads.
// Thread g holds W_hh row g as 32 packed u64. G inputs for step t+1 are
// prefetched into registers at the top of step t (off the critical path).
// Gate work item r: idx = r*192+g (<512), s = idx>>6 (seq), d = idx&63.
__global__ void __launch_bounds__(192) scan_kernel(const float* __restrict__ Whh,
                                                   const float* __restrict__ bhh) {
    const int blk   = blockIdx.x;
    const int axis  = blk >> 8;
    const int lb    = (blk & 255) * 4;        // first of 4 lines (0..1023)
    const int b     = lb >> 7;
    const int lane0 = lb & 127;
    const int g     = threadIdx.x;

    __shared__ __align__(16) float h2[8][64];
    __shared__ float hg[8][192];

    u64 w2[32];
    {
        const float2* wr = (const float2*)(Whh + g * 64);
        #pragma unroll
        for (int k = 0; k < 32; k++) { float2 w = wr[k]; w2[k] = pack2(w.x, w.y); }
    }
    const float bh = bhh[g];

    for (int i = g; i < 512; i += 192) ((float*)h2)[i] = 0.f;
    __syncthreads();

    const float* Gb   = g_G + (size_t)b * HW_ * 192;
    float* outS       = g_Hs[axis] + (size_t)b * HW_ * 64;
    const int pstride = axis ? 128 : 1;

    int it_s[3], it_d[3], it_pb[3], it_dir[3];
    bool it_v[3];
    #pragma unroll
    for (int r = 0; r < 3; r++) {
        const int idx = r * 192 + g;
        it_v[r]   = idx < 512;
        const int s = (idx >> 6) & 7;
        it_s[r]   = s;
        it_d[r]   = idx & 63;
        it_dir[r] = s & 1;
        const int li = s >> 1;
        it_pb[r]  = axis ? (lane0 + li) : (lane0 + li) * 128;
    }

    float cx[3], cz[3], cn[3];
    #pragma unroll
    for (int r = 0; r < 3; r++) {
        cx[r] = cz[r] = cn[r] = 0.f;
        if (it_v[r]) {
            const int tt = it_dir[r] ? 127 : 0;
            const float* Gp = Gb + (size_t)(it_pb[r] + tt * pstride) * 192 + it_d[r];
            cx[r] = __ldg(Gp); cz[r] = __ldg(Gp + 64); cn[r] = __ldg(Gp + 128);
        }
    }

    for (int t = 0; t < 128; t++) {
        // prefetch G for step t+1 (long-latency loads overlap matvec + barrier)
        float nx[3], nz[3], nn[3];
        {
            const int tq = (t + 1) & 127;
            #pragma unroll
            for (int r = 0; r < 3; r++) {
                nx[r] = nz[r] = nn[r] = 0.f;
                if (it_v[r]) {
                    const int tt = it_dir[r] ? 127 - tq : tq;
                    const float* Gp = Gb + (size_t)(it_pb[r] + tt * pstride) * 192 + it_d[r];
                    nx[r] = __ldg(Gp); nz[r] = __ldg(Gp + 64); nn[r] = __ldg(Gp + 128);
                }
            }
        }

        // matvec: hg[s][g] = bh + Whh[g] . h2[s], 8 independent chains
        u64 acc[8];
        #pragma unroll
        for (int s = 0; s < 8; s++) acc[s] = 0ULL;
        #pragma unroll
        for (int kk = 0; kk < 16; kk++) {
            longlong2 hv[8];
            #pragma unroll
            for (int s = 0; s < 8; s++) hv[s] = ((const longlong2*)h2[s])[kk];
            #pragma unroll
            for (int s = 0; s < 8; s++) fma2(acc[s], w2[2 * kk], (u64)hv[s].x);
            #pragma unroll
            for (int s = 0; s < 8; s++) fma2(acc[s], w2[2 * kk + 1], (u64)hv[s].y);
        }
        #pragma unroll
        for (int s = 0; s < 8; s++) {
            float2 f = unpack2(acc[s]);
            hg[s][g] = bh + f.x + f.y;
        }
        __syncthreads();

        // gate phase
        #pragma unroll
        for (int r = 0; r < 3; r++) {
            if (it_v[r]) {
                const int s = it_s[r], d = it_d[r];
                const int tt = it_dir[r] ? 127 - t : t;
                const int p  = it_pb[r] + tt * pstride;
                const float rr = sigm(cx[r] + hg[s][d]);
                const float zz = sigm(cz[r] + hg[s][64 + d]);
                const float pre = cn[r] + rr * hg[s][128 + d];
                const float nv = 2.f / (1.f + __expf(-2.f * pre)) - 1.f;   // tanh
                const float hnew = (1.f - zz) * nv + zz * h2[s][d];
                h2[s][d] = hnew;
                float* o = outS + (size_t)p * 64 + d;
                if (t < 64) *o = hnew;        // first writer of this pixel
                else        *o = *o + hnew;   // second writer accumulates
            }
        }
        __syncthreads();

        #pragma unroll
        for (int r = 0; r < 3; r++) { cx[r] = nx[r]; cz[r] = nz[r]; cn[r] = nn[r]; }
    }
}

// ---------------- kernel 4: out = Wo @ avg(h) + bo ----------------
// block: 64 px x 64 ch, K=64. 128 threads: tx=tid&15 -> 4 px, ty=tid>>4 -> 8 ch.
// Weights duplicated in smem as (w,w) float2 -> zero packing movs in K-loop.
// Dynamic smem: sH[64][68] floats + sWd[64][64] float2 = 50176 B.
__global__ void __launch_bounds__(128) out_gemm_kernel(const float* __restrict__ bo,
                                                       float* __restrict__ out) {
    extern __shared__ __align__(16) char smem[];
    float*  sH  = (float*)smem;                         // [64][68]
    float2* sWd = (float2*)(smem + 64 * 68 * 4);        // [64][64]

    const int bx = blockIdx.x;            // 0..2047
    const int b  = bx >> 8;
    const int p0 = (bx & 255) * 64;
    const int c0 = blockIdx.y * 64;
    const int tid = threadIdx.x;
    const int tx = tid & 15;              // 4-pixel group
    const int ty = tid >> 4;              // 8-channel group

    const size_t base = ((size_t)b * HW_ + p0) * 64;
    const float* hH = g_Hs[0] + base;
    const float* hV = g_Hs[1] + base;

    #pragma unroll
    for (int i = 0; i < 32; i++) {
        int lin = tid + i * 128;                       // 4096 elems
        int pp = lin >> 6, dd = lin & 63;              // dd fast -> coalesced reads
        sH[dd * 68 + pp] = 0.25f * (hH[(size_t)pp * 64 + dd] + hV[(size_t)pp * 64 + dd]);
    }
    #pragma unroll
    for (int i = 0; i < 32; i++) {
        int lin = tid + i * 128;
        int dd = lin >> 6, cc = lin & 63;
        float w = g_Wot[dd * 192 + c0 + cc];
        sWd[dd * 64 + cc] = make_float2(w, w);
    }
    __syncthreads();

    u64 acc[2][8];                                      // [pixel-pair][channel]
    #pragma unroll
    for (int p = 0; p < 2; p++)
        #pragma unroll
        for (int j = 0; j < 8; j++) acc[p][j] = 0ULL;

    #pragma unroll
    for (int dd = 0; dd < 64; dd++) {
        longlong2 a = *(const longlong2*)&sH[dd * 68 + 4 * tx];     // 16B-aligned (68*4=272)
        const longlong2* wp = (const longlong2*)&sWd[dd * 64 + 8 * ty]; // warp-broadcast
        longlong2 w01 = wp[0], w23 = wp[1], w45 = wp[2], w67 = wp[3];
        u64 wd[8] = { (u64)w01.x, (u64)w01.y, (u64)w23.x, (u64)w23.y,
                      (u64)w45.x, (u64)w45.y, (u64)w67.x, (u64)w67.y };
        #pragma unroll
        for (int j = 0; j < 8; j++) {
            fma2(acc[0][j], wd[j], (u64)a.x);
            fma2(acc[1][j], wd[j], (u64)a.y);
        }
    }

    #pragma unroll
    for (int j = 0; j < 8; j++) {
        const int c = c0 + 8 * ty + j;
        const float bv = bo[c];
        float2 lo = unpack2(acc[0][j]), hi = unpack2(acc[1][j]);
        float4 v = make_float4(lo.x + bv, lo.y + bv, hi.x + bv, hi.y + bv);
        *(float4*)&out[((size_t)b * 192 + c) * HW_ + p0 + 4 * tx] = v;   // coalesced
    }
}

// ---------------- launch ----------------
extern "C" void kernel_launch(void* const* d_in, const int* in_sizes, int n_in,
                              void* d_out, int out_size) {
    const float* x   = (const float*)d_in[0];
    const float* Wi  = (const float*)d_in[1];
    const float* bi  = (const float*)d_in[2];
    const float* Wih = (const float*)d_in[3];
    const float* Whh = (const float*)d_in[4];
    const float* bih = (const float*)d_in[5];
    const float* bhh = (const float*)d_in[6];
    const float* Wo  = (const float*)d_in[7];
    const float* bo  = (const float*)d_in[8];
    float* out = (float*)d_out;

    const int OUT_SMEM = 64 * 68 * 4 + 64 * 64 * 8;   // 50176 B
    cudaFuncSetAttribute(out_gemm_kernel, cudaFuncAttributeMaxDynamicSharedMemorySize, OUT_SMEM);

    prep_kernel<<<256, 192>>>(Wi, bi, Wih, bih, Wo);
    g_gemm_kernel<<<dim3(512, 3), 256>>>(x);
    scan_kernel<<<512, 192>>>(Whh, bhh);
    out_gemm_kernel<<<dim3(2048, 3), 128, OUT_SMEM>>>(bo, out);
}

// round 8
// speedup vs baseline: 1.0506x; 1.0313x over previous
#include <cuda_runtime.h>
#include <cstdint>
#include <cstddef>

#define B_   8
#define C_   192
#define HW_  16384
#define D_   64

typedef unsigned long long u64;

// ---------------- static device scratch (allocation-free rule) ----------------
__device__ float g_G[(size_t)B_ * HW_ * 192];      // gate pre-activations [pix][192]
__device__ float g_Hs[2][(size_t)B_ * HW_ * D_];   // per-axis hidden sum (fwd+bwd)
__device__ float g_Wc[C_ * 192];                   // folded input weights [c][g]
__device__ float g_bc[192];
__device__ float g_Wot[D_ * C_];                   // Wo^T [d][c]

// ---------------- f32x2 helpers ----------------
__device__ __forceinline__ void fma2(u64 &acc, u64 a, u64 b) {
    asm("fma.rn.f32x2 %0, %1, %2, %0;" : "+l"(acc) : "l"(a), "l"(b));
}
__device__ __forceinline__ u64 pack2(float x, float y) {
    u64 r; asm("mov.b64 %0, {%1, %2};" : "=l"(r) : "f"(x), "f"(y)); return r;
}
__device__ __forceinline__ float2 unpack2(u64 v) {
    float2 r; asm("mov.b64 {%0, %1}, %2;" : "=f"(r.x), "=f"(r.y) : "l"(v)); return r;
}
__device__ __forceinline__ float sigm(float x) { return 1.f / (1.f + __expf(-x)); }

// ---------------- kernel 1: fold weights ----------------
__global__ void prep_kernel(const float* __restrict__ Wi, const float* __restrict__ bi,
                            const float* __restrict__ Wih, const float* __restrict__ bih,
                            const float* __restrict__ Wo) {
    const int bid = blockIdx.x;
    const int c = threadIdx.x;
    if (bid < 192) {
        const int g = bid;
        float acc = 0.f;
        #pragma unroll 8
        for (int d = 0; d < 64; d++) acc += Wih[g * 64 + d] * Wi[d * 192 + c];
        g_Wc[c * 192 + g] = acc;
        if (c == 0) {
            float s = bih[g];
            for (int d = 0; d < 64; d++) s += Wih[g * 64 + d] * bi[d];
            g_bc[g] = s;
        }
    } else {
        const int d = bid - 192;
        g_Wot[d * 192 + c] = Wo[c * 64 + d];
    }
}

// ---------------- kernel 2: G = Wc @ x + bc  (f32x2, pixel pairs) ----------------
__global__ void __launch_bounds__(256) g_gemm_kernel(const float* __restrict__ x) {
    const int pblk = blockIdx.x;          // 0..511
    const int b  = pblk >> 6;
    const int p0 = (pblk & 63) * 256;
    const int g0 = blockIdx.y * 64;
    const int tid = threadIdx.x;
    const int tx = tid & 31;
    const int ty = tid >> 5;

    __shared__ __align__(16) float  sX[16][256];
    __shared__ __align__(16) float2 sWd[16][64];

    u64 acc[2][2][8];
    #pragma unroll
    for (int h = 0; h < 2; h++)
        #pragma unroll
        for (int p = 0; p < 2; p++)
            #pragma unroll
            for (int j = 0; j < 8; j++) acc[h][p][j] = 0ULL;

    const float* xb = x + (size_t)b * C_ * HW_ + p0;

    for (int c0i = 0; c0i < 192; c0i += 16) {
        #pragma unroll
        for (int i = 0; i < 4; i++) {
            int lin = tid + i * 256;
            int cc = lin >> 6, q4 = lin & 63;
            ((float4*)sX[cc])[q4] = *(const float4*)(xb + (size_t)(c0i + cc) * HW_ + q4 * 4);
        }
        #pragma unroll
        for (int i = 0; i < 4; i++) {
            int lin = tid + i * 256;
            int cc = lin >> 6, gg = lin & 63;
            float w = g_Wc[(c0i + cc) * 192 + g0 + gg];
            sWd[cc][gg] = make_float2(w, w);
        }
        __syncthreads();
        #pragma unroll
        for (int cc = 0; cc < 16; cc++) {
            longlong2 xA = *(const longlong2*)&sX[cc][4 * tx];
            longlong2 xB = *(const longlong2*)&sX[cc][128 + 4 * tx];
            const longlong2* wp = (const longlong2*)&sWd[cc][8 * ty];
            longlong2 w01 = wp[0], w23 = wp[1], w45 = wp[2], w67 = wp[3];
            u64 wd[8] = { (u64)w01.x, (u64)w01.y, (u64)w23.x, (u64)w23.y,
                          (u64)w45.x, (u64)w45.y, (u64)w67.x, (u64)w67.y };
            #pragma unroll
            for (int j = 0; j < 8; j++) {
                fma2(acc[0][0][j], wd[j], (u64)xA.x);
                fma2(acc[0][1][j], wd[j], (u64)xA.y);
                fma2(acc[1][0][j], wd[j], (u64)xB.x);
                fma2(acc[1][1][j], wd[j], (u64)xB.y);
            }
        }
        __syncthreads();
    }

    float bc[8];
    *(float4*)&bc[0] = *(const float4*)&g_bc[g0 + 8 * ty];
    *(float4*)&bc[4] = *(const float4*)&g_bc[g0 + 8 * ty + 4];

    #pragma unroll
    for (int h = 0; h < 2; h++) {
        #pragma unroll
        for (int p = 0; p < 2; p++) {
            const size_t q = (size_t)b * HW_ + p0 + h * 128 + 4 * tx + 2 * p;
            float2 v[8];
            #pragma unroll
            for (int j = 0; j < 8; j++) v[j] = unpack2(acc[h][p][j]);
            float* gp0 = &g_G[q * 192 + g0 + 8 * ty];
            ((float4*)gp0)[0] = make_float4(v[0].x + bc[0], v[1].x + bc[1], v[2].x + bc[2], v[3].x + bc[3]);
            ((float4*)gp0)[1] = make_float4(v[4].x + bc[4], v[5].x + bc[5], v[6].x + bc[6], v[7].x + bc[7]);
            float* gp1 = gp0 + 192;
            ((float4*)gp1)[0] = make_float4(v[0].y + bc[0], v[1].y + bc[1], v[2].y + bc[2], v[3].y + bc[3]);
            ((float4*)gp1)[1] = make_float4(v[4].y + bc[4], v[5].y + bc[5], v[6].y + bc[6], v[7].y + bc[7]);
        }
    }
}

// ---------------- kernel 3: GRU scans, 2 lines x (fwd+bwd) = 4 seqs per block ----------------
// 1024 blocks: [0,512) horizontal line-pairs, [512,1024) vertical. 192 threads.
// Thread g: W_hh row g as 32 packed u64 (64 regs), 4 independent fma2 chains.
// seq s = 2*li + dir (li in {0,1}, dir 0=fwd 1=bwd). Gate items: 4*64=256,
// thread g handles item g (s=g>>6) and, if g<64, item 192+g (s=3).
// G for step t+1 prefetched before the matvec (latency hidden under FMAs).
__global__ void __launch_bounds__(192, 2) scan_kernel(const float* __restrict__ Whh,
                                                      const float* __restrict__ bhh) {
    const int blk   = blockIdx.x;
    const int axis  = blk >> 9;
    const int lb    = (blk & 511) * 2;        // first of 2 lines (0..1022)
    const int b     = lb >> 7;
    const int lane0 = lb & 127;
    const int g     = threadIdx.x;

    __shared__ __align__(16) float h2[4][64];
    __shared__ float hg[4][192];

    u64 w2[32];
    {
        const float2* wr = (const float2*)(Whh + g * 64);
        #pragma unroll
        for (int k = 0; k < 32; k++) { float2 w = wr[k]; w2[k] = pack2(w.x, w.y); }
    }
    const float bh = bhh[g];

    for (int i = g; i < 256; i += 192) ((float*)h2)[i] = 0.f;
    __syncthreads();

    const float* Gb = g_G + (size_t)b * HW_ * 192;
    float* outS = g_Hs[axis] + (size_t)b * HW_ * 64;

    // item 0: all threads
    const int s0   = g >> 6;
    const int d0   = g & 63;
    const int dir0 = s0 & 1;
    const int lineA = lane0 + (s0 >> 1);
    // item 1: g<64, s=3 (line lane0+1, bwd)
    const bool v1  = (g < 64);
    const int lineB = lane0 + 1;

    // pixel index helper (flattened manually for speed)
    const int pm = axis ? 128 : 1;           // multiplier on tt
    const int pa0 = axis ? lineA : lineA * 128;
    const int pa1 = axis ? lineB : lineB * 128;

    // initial G loads (t=0)
    float cx0, cz0, cn0, cx1 = 0.f, cz1 = 0.f, cn1 = 0.f;
    {
        const int tt = dir0 ? 127 : 0;
        const float* Gp = Gb + (size_t)(pa0 + tt * pm) * 192 + d0;
        cx0 = __ldg(Gp); cz0 = __ldg(Gp + 64); cn0 = __ldg(Gp + 128);
        if (v1) {
            const float* Gq = Gb + (size_t)(pa1 + 127 * pm) * 192 + g;
            cx1 = __ldg(Gq); cz1 = __ldg(Gq + 64); cn1 = __ldg(Gq + 128);
        }
    }

    for (int t = 0; t < 128; t++) {
        // ---- prefetch G for step t+1 (overlaps the matvec below) ----
        float nx0, nz0, nn0, nx1 = 0.f, nz1 = 0.f, nn1 = 0.f;
        {
            const int tq = (t + 1) & 127;
            const int tt = dir0 ? 127 - tq : tq;
            const float* Gp = Gb + (size_t)(pa0 + tt * pm) * 192 + d0;
            nx0 = __ldg(Gp); nz0 = __ldg(Gp + 64); nn0 = __ldg(Gp + 128);
            if (v1) {
                const float* Gq = Gb + (size_t)(pa1 + (127 - tq) * pm) * 192 + g;
                nx1 = __ldg(Gq); nz1 = __ldg(Gq + 64); nn1 = __ldg(Gq + 128);
            }
        }

        // ---- matvec: hg[s][g] = bh + Whh[g] . h2[s], 4 independent fma2 chains ----
        u64 a0 = 0ULL, a1 = 0ULL, a2 = 0ULL, a3 = 0ULL;
        #pragma unroll
        for (int kk = 0; kk < 16; kk++) {
            longlong2 hv0 = ((const longlong2*)h2[0])[kk];
            longlong2 hv1 = ((const longlong2*)h2[1])[kk];
            longlong2 hv2 = ((const longlong2*)h2[2])[kk];
            longlong2 hv3 = ((const longlong2*)h2[3])[kk];
            const u64 wA = w2[2 * kk], wB = w2[2 * kk + 1];
            fma2(a0, wA, (u64)hv0.x); fma2(a1, wA, (u64)hv1.x);
            fma2(a2, wA, (u64)hv2.x); fma2(a3, wA, (u64)hv3.x);
            fma2(a0, wB, (u64)hv0.y); fma2(a1, wB, (u64)hv1.y);
            fma2(a2, wB, (u64)hv2.y); fma2(a3, wB, (u64)hv3.y);
        }
        {
            float2 f;
            f = unpack2(a0); hg[0][g] = bh + f.x + f.y;
            f = unpack2(a1); hg[1][g] = bh + f.x + f.y;
            f = unpack2(a2); hg[2][g] = bh + f.x + f.y;
            f = unpack2(a3); hg[3][g] = bh + f.x + f.y;
        }
        __syncthreads();

        // ---- gate item 0 ----
        {
            const int tt = dir0 ? 127 - t : t;
            const int p  = pa0 + tt * pm;
            const float rr = sigm(cx0 + hg[s0][d0]);
            const float zz = sigm(cz0 + hg[s0][64 + d0]);
            const float pre = cn0 + rr * hg[s0][128 + d0];
            const float nv = 2.f / (1.f + __expf(-2.f * pre)) - 1.f;   // tanh
            const float hnew = (1.f - zz) * nv + zz * h2[s0][d0];
            h2[s0][d0] = hnew;
            float* o = outS + (size_t)p * 64 + d0;
            if (t < 64) *o = hnew;
            else        *o = *o + hnew;
        }
        // ---- gate item 1 (s=3, bwd on line lane0+1) ----
        if (v1) {
            const int tt = 127 - t;
            const int p  = pa1 + tt * pm;
            const float rr = sigm(cx1 + hg[3][g]);
            const float zz = sigm(cz1 + hg[3][64 + g]);
            const float pre = cn1 + rr * hg[3][128 + g];
            const float nv = 2.f / (1.f + __expf(-2.f * pre)) - 1.f;
            const float hnew = (1.f - zz) * nv + zz * h2[3][g];
            h2[3][g] = hnew;
            float* o = outS + (size_t)p * 64 + g;
            if (t < 64) *o = hnew;
            else        *o = *o + hnew;
        }
        __syncthreads();

        cx0 = nx0; cz0 = nz0; cn0 = nn0;
        cx1 = nx1; cz1 = nz1; cn1 = nn1;
    }
}

// ---------------- kernel 4: out = Wo @ avg(h) + bo  (R4 version, best measured) ----------------
__global__ void __launch_bounds__(256) out_gemm_kernel(const float* __restrict__ bo,
                                                       float* __restrict__ out) {
    const int bx = blockIdx.x;
    const int b  = bx >> 8;
    const int p0 = (bx & 255) * 64;
    const int c0 = blockIdx.y * 64;
    const int tid = threadIdx.x;
    const int tx = tid & 15;
    const int ty = tid >> 4;

    __shared__ __align__(16) float sH[64][66];
    __shared__ __align__(16) float sW[64][64];

    const size_t base = ((size_t)b * HW_ + p0) * 64;
    const float* hH = g_Hs[0] + base;
    const float* hV = g_Hs[1] + base;

    #pragma unroll
    for (int i = 0; i < 16; i++) {
        int lin = tid + i * 256;
        int pp = lin >> 6, dd = lin & 63;
        sH[dd][pp] = 0.25f * (hH[(size_t)pp * 64 + dd] + hV[(size_t)pp * 64 + dd]);
    }
    #pragma unroll
    for (int i = 0; i < 16; i++) {
        int lin = tid + i * 256;
        int dd = lin >> 6, cc = lin & 63;
        sW[dd][cc] = g_Wot[dd * 192 + c0 + cc];
    }
    __syncthreads();

    u64 acc[4][2];
    #pragma unroll
    for (int j = 0; j < 4; j++) { acc[j][0] = 0ULL; acc[j][1] = 0ULL; }

    #pragma unroll
    for (int dd = 0; dd < 64; dd++) {
        const u64* ap = (const u64*)&sH[dd][4 * tx];
        u64 aLo = ap[0], aHi = ap[1];
        float4 wv = *(const float4*)&sW[dd][4 * ty];
        u64 wd[4] = { pack2(wv.x, wv.x), pack2(wv.y, wv.y),
                      pack2(wv.z, wv.z), pack2(wv.w, wv.w) };
        #pragma unroll
        for (int j = 0; j < 4; j++) {
            fma2(acc[j][0], wd[j], aLo);
            fma2(acc[j][1], wd[j], aHi);
        }
    }

    #pragma unroll
    for (int j = 0; j < 4; j++) {
        const int c = c0 + 4 * ty + j;
        const float bv = bo[c];
        float2 lo = unpack2(acc[j][0]), hi = unpack2(acc[j][1]);
        float4 v = make_float4(lo.x + bv, lo.y + bv, hi.x + bv, hi.y + bv);
        *(float4*)&out[((size_t)b * 192 + c) * HW_ + p0 + 4 * tx] = v;
    }
}

// ---------------- launch ----------------
extern "C" void kernel_launch(void* const* d_in, const int* in_sizes, int n_in,
                              void* d_out, int out_size) {
    const float* x   = (const float*)d_in[0];
    const float* Wi  = (const float*)d_in[1];
    const float* bi  = (const float*)d_in[2];
    const float* Wih = (const float*)d_in[3];
    const float* Whh = (const float*)d_in[4];
    const float* bih = (const float*)d_in[5];
    const float* bhh = (const float*)d_in[6];
    const float* Wo  = (const float*)d_in[7];
    const float* bo  = (const float*)d_in[8];
    float* out = (float*)d_out;

    prep_kernel<<<256, 192>>>(Wi, bi, Wih, bih, Wo);
    g_gemm_kernel<<<dim3(512, 3), 256>>>(x);
    scan_kernel<<<1024, 192>>>(Whh, bhh);
    out_gemm_kernel<<<dim3(2048, 3), 256>>>(bo, out);
}

// round 9
// speedup vs baseline: 1.1104x; 1.0569x over previous
#include <cuda_runtime.h>
#include <cuda_fp16.h>
#include <cstdint>
#include <cstddef>

#define B_   8
#define C_   192
#define HW_  16384
#define D_   64

typedef unsigned long long u64;
typedef unsigned int u32;

// ---------------- static device scratch (allocation-free rule) ----------------
__device__ __half g_G[(size_t)B_ * HW_ * 192];     // gate pre-activations, fp16 (50MB, L2-resident)
__device__ float  g_Hs[2][(size_t)B_ * HW_ * D_];  // per-axis hidden sum (fwd+bwd)
__device__ float  g_Wc[C_ * 192];                  // folded input weights [c][g]
__device__ float  g_bc[192];
__device__ float  g_Wot[D_ * C_];                  // Wo^T [d][c]

// ---------------- f32x2 helpers ----------------
__device__ __forceinline__ void fma2(u64 &acc, u64 a, u64 b) {
    asm("fma.rn.f32x2 %0, %1, %2, %0;" : "+l"(acc) : "l"(a), "l"(b));
}
__device__ __forceinline__ u64 pack2(float x, float y) {
    u64 r; asm("mov.b64 %0, {%1, %2};" : "=l"(r) : "f"(x), "f"(y)); return r;
}
__device__ __forceinline__ float2 unpack2(u64 v) {
    float2 r; asm("mov.b64 {%0, %1}, %2;" : "=f"(r.x), "=f"(r.y) : "l"(v)); return r;
}
__device__ __forceinline__ float sigm(float x) { return 1.f / (1.f + __expf(-x)); }
__device__ __forceinline__ u32 h2u(__half2 h) { return *reinterpret_cast<u32*>(&h); }

// ---------------- kernel 1: fold weights ----------------
__global__ void prep_kernel(const float* __restrict__ Wi, const float* __restrict__ bi,
                            const float* __restrict__ Wih, const float* __restrict__ bih,
                            const float* __restrict__ Wo) {
    const int bid = blockIdx.x;
    const int c = threadIdx.x;
    if (bid < 192) {
        const int g = bid;
        float acc = 0.f;
        #pragma unroll 8
        for (int d = 0; d < 64; d++) acc += Wih[g * 64 + d] * Wi[d * 192 + c];
        g_Wc[c * 192 + g] = acc;
        if (c == 0) {
            float s = bih[g];
            for (int d = 0; d < 64; d++) s += Wih[g * 64 + d] * bi[d];
            g_bc[g] = s;
        }
    } else {
        const int d = bid - 192;
        g_Wot[d * 192 + c] = Wo[c * 64 + d];
    }
}

// ---------------- kernel 2: G = Wc @ x + bc  (f32x2, fp16 stores) ----------------
// grid (3, 512): blockIdx.x = gate group (fastest -> adjacent blocks share x via L2).
__global__ void __launch_bounds__(256) g_gemm_kernel(const float* __restrict__ x) {
    const int pblk = blockIdx.y;          // 0..511
    const int b  = pblk >> 6;
    const int p0 = (pblk & 63) * 256;
    const int g0 = blockIdx.x * 64;
    const int tid = threadIdx.x;
    const int tx = tid & 31;
    const int ty = tid >> 5;

    __shared__ __align__(16) float  sX[16][256];
    __shared__ __align__(16) float2 sWd[16][64];

    u64 acc[2][2][8];
    #pragma unroll
    for (int h = 0; h < 2; h++)
        #pragma unroll
        for (int p = 0; p < 2; p++)
            #pragma unroll
            for (int j = 0; j < 8; j++) acc[h][p][j] = 0ULL;

    const float* xb = x + (size_t)b * C_ * HW_ + p0;

    for (int c0i = 0; c0i < 192; c0i += 16) {
        #pragma unroll
        for (int i = 0; i < 4; i++) {
            int lin = tid + i * 256;
            int cc = lin >> 6, q4 = lin & 63;
            ((float4*)sX[cc])[q4] = *(const float4*)(xb + (size_t)(c0i + cc) * HW_ + q4 * 4);
        }
        #pragma unroll
        for (int i = 0; i < 4; i++) {
            int lin = tid + i * 256;
            int cc = lin >> 6, gg = lin & 63;
            float w = g_Wc[(c0i + cc) * 192 + g0 + gg];
            sWd[cc][gg] = make_float2(w, w);
        }
        __syncthreads();
        #pragma unroll
        for (int cc = 0; cc < 16; cc++) {
            longlong2 xA = *(const longlong2*)&sX[cc][4 * tx];
            longlong2 xB = *(const longlong2*)&sX[cc][128 + 4 * tx];
            const longlong2* wp = (const longlong2*)&sWd[cc][8 * ty];
            longlong2 w01 = wp[0], w23 = wp[1], w45 = wp[2], w67 = wp[3];
            u64 wd[8] = { (u64)w01.x, (u64)w01.y, (u64)w23.x, (u64)w23.y,
                          (u64)w45.x, (u64)w45.y, (u64)w67.x, (u64)w67.y };
            #pragma unroll
            for (int j = 0; j < 8; j++) {
                fma2(acc[0][0][j], wd[j], (u64)xA.x);
                fma2(acc[0][1][j], wd[j], (u64)xA.y);
                fma2(acc[1][0][j], wd[j], (u64)xB.x);
                fma2(acc[1][1][j], wd[j], (u64)xB.y);
            }
        }
        __syncthreads();
    }

    float bc[8];
    *(float4*)&bc[0] = *(const float4*)&g_bc[g0 + 8 * ty];
    *(float4*)&bc[4] = *(const float4*)&g_bc[g0 + 8 * ty + 4];

    #pragma unroll
    for (int h = 0; h < 2; h++) {
        #pragma unroll
        for (int p = 0; p < 2; p++) {
            const size_t q = (size_t)b * HW_ + p0 + h * 128 + 4 * tx + 2 * p;
            float2 v[8];
            #pragma unroll
            for (int j = 0; j < 8; j++) v[j] = unpack2(acc[h][p][j]);
            // pixel q  (x lanes) and pixel q+1 (y lanes), 8 halves = 16B each
            uint4 s0, s1;
            s0.x = h2u(__floats2half2_rn(v[0].x + bc[0], v[1].x + bc[1]));
            s0.y = h2u(__floats2half2_rn(v[2].x + bc[2], v[3].x + bc[3]));
            s0.z = h2u(__floats2half2_rn(v[4].x + bc[4], v[5].x + bc[5]));
            s0.w = h2u(__floats2half2_rn(v[6].x + bc[6], v[7].x + bc[7]));
            s1.x = h2u(__floats2half2_rn(v[0].y + bc[0], v[1].y + bc[1]));
            s1.y = h2u(__floats2half2_rn(v[2].y + bc[2], v[3].y + bc[3]));
            s1.z = h2u(__floats2half2_rn(v[4].y + bc[4], v[5].y + bc[5]));
            s1.w = h2u(__floats2half2_rn(v[6].y + bc[6], v[7].y + bc[7]));
            *(uint4*)(&g_G[q * 192 + g0 + 8 * ty])       = s0;
            *(uint4*)(&g_G[(q + 1) * 192 + g0 + 8 * ty]) = s1;
        }
    }
}

// ---------------- kernel 3: GRU scans, 2 lines x (fwd+bwd) per block ----------------
// grid 512 per axis. 192 threads. Thread g: W_hh row g as 32 packed u64.
// Hs accumulated in smem line buffers (64KB), flushed coalesced at the end.
// G (fp16, L2-resident) prefetched one step ahead.
__global__ void __launch_bounds__(192, 2) scan_kernel(const float* __restrict__ Whh,
                                                      const float* __restrict__ bhh,
                                                      const int axis) {
    extern __shared__ __align__(16) float smem[];
    float* h2  = smem;                 // [4][64]
    float* hg  = smem + 256;           // [4][192]
    float* buf = smem + 256 + 768;     // [2][128][64]

    const int blk   = blockIdx.x;
    const int lb    = blk * 2;                // first of 2 lines (0..1022)
    const int b     = lb >> 7;
    const int lane0 = lb & 127;
    const int g     = threadIdx.x;

    u64 w2[32];
    {
        const float2* wr = (const float2*)(Whh + g * 64);
        #pragma unroll
        for (int k = 0; k < 32; k++) { float2 w = wr[k]; w2[k] = pack2(w.x, w.y); }
    }
    const float bh = bhh[g];

    for (int i = g; i < 256; i += 192) h2[i] = 0.f;
    __syncthreads();

    const __half* Gb = g_G + (size_t)b * HW_ * 192;
    float* outS = g_Hs[axis] + (size_t)b * HW_ * 64;

    // item 0: all threads. s0 in {0,1,2}: (line lane0,fwd),(lane0,bwd),(lane0+1,fwd)
    const int s0    = g >> 6;
    const int d0    = g & 63;
    const int dir0  = s0 & 1;
    const int li0   = s0 >> 1;
    const int lineA = lane0 + li0;
    // item 1: g<64 -> s=3: (line lane0+1, bwd)
    const bool v1   = (g < 64);
    const int lineB = lane0 + 1;

    const int pm  = axis ? 128 : 1;
    const int pa0 = axis ? lineA : lineA * 128;
    const int pa1 = axis ? lineB : lineB * 128;

    // initial G loads (t=0)
    float cx0, cz0, cn0, cx1 = 0.f, cz1 = 0.f, cn1 = 0.f;
    {
        const int tt = dir0 ? 127 : 0;
        const __half* Gp = Gb + (size_t)(pa0 + tt * pm) * 192 + d0;
        cx0 = __half2float(__ldg(Gp));
        cz0 = __half2float(__ldg(Gp + 64));
        cn0 = __half2float(__ldg(Gp + 128));
        if (v1) {
            const __half* Gq = Gb + (size_t)(pa1 + 127 * pm) * 192 + g;
            cx1 = __half2float(__ldg(Gq));
            cz1 = __half2float(__ldg(Gq + 64));
            cn1 = __half2float(__ldg(Gq + 128));
        }
    }

    for (int t = 0; t < 128; t++) {
        // ---- prefetch G for step t+1 ----
        float nx0, nz0, nn0, nx1 = 0.f, nz1 = 0.f, nn1 = 0.f;
        {
            const int tq = (t + 1) & 127;
            const int tt = dir0 ? 127 - tq : tq;
            const __half* Gp = Gb + (size_t)(pa0 + tt * pm) * 192 + d0;
            nx0 = __half2float(__ldg(Gp));
            nz0 = __half2float(__ldg(Gp + 64));
            nn0 = __half2float(__ldg(Gp + 128));
            if (v1) {
                const __half* Gq = Gb + (size_t)(pa1 + (127 - tq) * pm) * 192 + g;
                nx1 = __half2float(__ldg(Gq));
                nz1 = __half2float(__ldg(Gq + 64));
                nn1 = __half2float(__ldg(Gq + 128));
            }
        }

        // ---- matvec: hg[s][g] = bh + Whh[g] . h2[s], 4 independent fma2 chains ----
        u64 a0 = 0ULL, a1 = 0ULL, a2 = 0ULL, a3 = 0ULL;
        #pragma unroll
        for (int kk = 0; kk < 16; kk++) {
            longlong2 hv0 = ((const longlong2*)(h2))[kk];
            longlong2 hv1 = ((const longlong2*)(h2 + 64))[kk];
            longlong2 hv2 = ((const longlong2*)(h2 + 128))[kk];
            longlong2 hv3 = ((const longlong2*)(h2 + 192))[kk];
            const u64 wA = w2[2 * kk], wB = w2[2 * kk + 1];
            fma2(a0, wA, (u64)hv0.x); fma2(a1, wA, (u64)hv1.x);
            fma2(a2, wA, (u64)hv2.x); fma2(a3, wA, (u64)hv3.x);
            fma2(a0, wB, (u64)hv0.y); fma2(a1, wB, (u64)hv1.y);
            fma2(a2, wB, (u64)hv2.y); fma2(a3, wB, (u64)hv3.y);
        }
        {
            float2 f;
            f = unpack2(a0); hg[0 * 192 + g] = bh + f.x + f.y;
            f = unpack2(a1); hg[1 * 192 + g] = bh + f.x + f.y;
            f = unpack2(a2); hg[2 * 192 + g] = bh + f.x + f.y;
            f = unpack2(a3); hg[3 * 192 + g] = bh + f.x + f.y;
        }
        __syncthreads();

        // ---- gate item 0 ----
        {
            const int tt = dir0 ? 127 - t : t;
            const float rr = sigm(cx0 + hg[s0 * 192 + d0]);
            const float zz = sigm(cz0 + hg[s0 * 192 + 64 + d0]);
            const float pre = cn0 + rr * hg[s0 * 192 + 128 + d0];
            const float nv = 2.f / (1.f + __expf(-2.f * pre)) - 1.f;   // tanh
            const float hnew = (1.f - zz) * nv + zz * h2[s0 * 64 + d0];
            h2[s0 * 64 + d0] = hnew;
            float* o = buf + li0 * 8192 + tt * 64 + d0;
            if (t < 64) *o = hnew;        // first contribution to this pixel
            else        *o = *o + hnew;   // second contribution (smem accumulate)
        }
        // ---- gate item 1 (s=3: line lane0+1, bwd) ----
        if (v1) {
            const int tt = 127 - t;
            const float rr = sigm(cx1 + hg[3 * 192 + g]);
            const float zz = sigm(cz1 + hg[3 * 192 + 64 + g]);
            const float pre = cn1 + rr * hg[3 * 192 + 128 + g];
            const float nv = 2.f / (1.f + __expf(-2.f * pre)) - 1.f;
            const float hnew = (1.f - zz) * nv + zz * h2[3 * 64 + g];
            h2[3 * 64 + g] = hnew;
            float* o = buf + 8192 + tt * 64 + g;
            if (t < 64) *o = hnew;
            else        *o = *o + hnew;
        }
        __syncthreads();

        cx0 = nx0; cz0 = nz0; cn0 = nn0;
        cx1 = nx1; cz1 = nz1; cn1 = nn1;
    }

    // ---- flush line buffers to g_Hs (coalesced) ----
    for (int i = g; i < 2 * 128 * 64; i += 192) {
        const int li = i >> 13;
        const int rem = i & 8191;
        const int t = rem >> 6;
        const int d = rem & 63;
        const int line = lane0 + li;
        const int p = axis ? (t * 128 + line) : (line * 128 + t);
        outS[(size_t)p * 64 + d] = buf[i];
    }
}

// ---------------- kernel 4: out = Wo @ avg(h) + bo ----------------
__global__ void __launch_bounds__(256) out_gemm_kernel(const float* __restrict__ bo,
                                                       float* __restrict__ out) {
    const int bx = blockIdx.x;
    const int b  = bx >> 8;
    const int p0 = (bx & 255) * 64;
    const int c0 = blockIdx.y * 64;
    const int tid = threadIdx.x;
    const int tx = tid & 15;
    const int ty = tid >> 4;

    __shared__ __align__(16) float sH[64][66];
    __shared__ __align__(16) float sW[64][64];

    const size_t base = ((size_t)b * HW_ + p0) * 64;
    const float* hH = g_Hs[0] + base;
    const float* hV = g_Hs[1] + base;

    #pragma unroll
    for (int i = 0; i < 16; i++) {
        int lin = tid + i * 256;
        int pp = lin >> 6, dd = lin & 63;
        sH[dd][pp] = 0.25f * (hH[(size_t)pp * 64 + dd] + hV[(size_t)pp * 64 + dd]);
    }
    #pragma unroll
    for (int i = 0; i < 16; i++) {
        int lin = tid + i * 256;
        int dd = lin >> 6, cc = lin & 63;
        sW[dd][cc] = g_Wot[dd * 192 + c0 + cc];
    }
    __syncthreads();

    u64 acc[4][2];
    #pragma unroll
    for (int j = 0; j < 4; j++) { acc[j][0] = 0ULL; acc[j][1] = 0ULL; }

    #pragma unroll
    for (int dd = 0; dd < 64; dd++) {
        const u64* ap = (const u64*)&sH[dd][4 * tx];
        u64 aLo = ap[0], aHi = ap[1];
        float4 wv = *(const float4*)&sW[dd][4 * ty];
        u64 wd[4] = { pack2(wv.x, wv.x), pack2(wv.y, wv.y),
                      pack2(wv.z, wv.z), pack2(wv.w, wv.w) };
        #pragma unroll
        for (int j = 0; j < 4; j++) {
            fma2(acc[j][0], wd[j], aLo);
            fma2(acc[j][1], wd[j], aHi);
        }
    }

    #pragma unroll
    for (int j = 0; j < 4; j++) {
        const int c = c0 + 4 * ty + j;
        const float bv = bo[c];
        float2 lo = unpack2(acc[j][0]), hi = unpack2(acc[j][1]);
        float4 v = make_float4(lo.x + bv, lo.y + bv, hi.x + bv, hi.y + bv);
        *(float4*)&out[((size_t)b * 192 + c) * HW_ + p0 + 4 * tx] = v;
    }
}

// ---------------- launch ----------------
extern "C" void kernel_launch(void* const* d_in, const int* in_sizes, int n_in,
                              void* d_out, int out_size) {
    const float* x   = (const float*)d_in[0];
    const float* Wi  = (const float*)d_in[1];
    const float* bi  = (const float*)d_in[2];
    const float* Wih = (const float*)d_in[3];
    const float* Whh = (const float*)d_in[4];
    const float* bih = (const float*)d_in[5];
    const float* bhh = (const float*)d_in[6];
    const float* Wo  = (const float*)d_in[7];
    const float* bo  = (const float*)d_in[8];
    float* out = (float*)d_out;

    const int SCAN_SMEM = (256 + 768 + 2 * 128 * 64) * 4;   // 69632 B
    cudaFuncSetAttribute(scan_kernel, cudaFuncAttributeMaxDynamicSharedMemorySize, SCAN_SMEM);

    prep_kernel<<<256, 192>>>(Wi, bi, Wih, bih, Wo);
    g_gemm_kernel<<<dim3(3, 512), 256>>>(x);
    scan_kernel<<<512, 192, SCAN_SMEM>>>(Whh, bhh, 0);
    scan_kernel<<<512, 192, SCAN_SMEM>>>(Whh, bhh, 1);
    out_gemm_kernel<<<dim3(2048, 3), 256>>>(bo, out);
}